// round 15
// baseline (speedup 1.0000x reference)
#include <cuda_runtime.h>
#include <cuda_fp16.h>
#include <cstdint>

// IntraAgg: segment-mean neighbor aggregation, fp16-table path.
// K1 (fused): f32->fp16 table (16 floats/thread, measured-best) + bounds +
//             work-counter reset.
// K2: dynamic work-stealing (atomic segment counter), 2 warps/CTA,
//     __launch_bounds__(64,26) -> 52 resident warps/SM; per-warp barrier-free
//     cp.async ring, 4 commit groups x 2 rows, wait_group 3, pairwise HADD2
//     (the R14-proven consumer).
//   d_in[0] features    float32 [100000*256]
//   d_in[1] neigh_idx   int32   [524288]
//   d_in[2] segment_ids int32   [524288] (sorted ascending)
//   d_in[3] self_feats  float32 [16384*256]
// output: float32 [16384*512] = concat(self - agg, agg)

#define D_FEAT   256
#define N_BATCH  16384
#define N_NODES  100000
#define STAGES   8                // per-warp ring: 4 groups of 2 rows (4KB)
#define TPB      64               // 2 warps per CTA
#define WPB      2
#define ROW_B    (D_FEAT * 2)     // 512 bytes per fp16 row
#define CTAS_RES (26 * 148)       // exactly the resident set

__device__ int g_seg_start[N_BATCH + 1];
__device__ int g_counter;
__device__ __align__(16) __half g_feat_h[(size_t)N_NODES * D_FEAT];  // 51.2 MB

// Fused prep: 16 floats/thread f32->fp16 + segment bounds + counter reset.
__global__ void prep_kernel(const float* __restrict__ f, int n16,
                            const int* __restrict__ seg_ids, int n_edges)
{
    const int i = blockIdx.x * blockDim.x + threadIdx.x;

    if (i == 0) g_counter = 0;

    if (i < n16) {
        const float4* s = reinterpret_cast<const float4*>(f) + 4 * (size_t)i;
        const float4 a = __ldcs(s);
        const float4 c = __ldcs(s + 1);
        const float4 d = __ldcs(s + 2);
        const float4 e = __ldcs(s + 3);
        __half2 h[8];
        h[0] = __floats2half2_rn(a.x, a.y);  h[1] = __floats2half2_rn(a.z, a.w);
        h[2] = __floats2half2_rn(c.x, c.y);  h[3] = __floats2half2_rn(c.z, c.w);
        h[4] = __floats2half2_rn(d.x, d.y);  h[5] = __floats2half2_rn(d.z, d.w);
        h[6] = __floats2half2_rn(e.x, e.y);  h[7] = __floats2half2_rn(e.z, e.w);
        uint4* dst = reinterpret_cast<uint4*>(g_feat_h + 16 * (size_t)i);
        dst[0] = reinterpret_cast<const uint4*>(h)[0];
        dst[1] = reinterpret_cast<const uint4*>(h)[1];
    }

    if (i < n_edges) {
        const int s_cur  = __ldg(seg_ids + i);
        const int s_prev = (i == 0) ? -1 : __ldg(seg_ids + i - 1);
        for (int b = s_prev + 1; b <= s_cur; ++b)
            g_seg_start[b] = i;
        if (i == n_edges - 1)
            for (int b = s_cur + 1; b <= N_BATCH; ++b)
                g_seg_start[b] = n_edges;
    }
}

__device__ __forceinline__ uint32_t smem_u32(const void* p)
{
    return (uint32_t)__cvta_generic_to_shared(p);
}

__device__ __forceinline__ void cp16(uint32_t dst, const void* src)
{
    asm volatile("cp.async.cg.shared.global [%0], [%1], 16;"
                 :: "r"(dst), "l"(src) : "memory");
}

__device__ __forceinline__ void cp_commit()
{
    asm volatile("cp.async.commit_group;" ::: "memory");
}

__global__ __launch_bounds__(TPB, 26) void intra_agg_kernel(
    const int* __restrict__ neigh_idx,
    const float* __restrict__ self_feats,
    float* __restrict__ out)
{
    // warp-private ring; lane owns 16B of each 512B row; no cross-thread smem
    // sharing -> no barriers. Warps draw segments from a global counter.
    __shared__ __align__(16) float4 buf[WPB][STAGES][32];

    const int w    = threadIdx.x >> 5;
    const int lane = threadIdx.x & 31;
    const char* fbase = reinterpret_cast<const char*>(g_feat_h);
    const size_t col = (size_t)lane * 16;

    while (true) {
        int b;
        if (lane == 0) b = atomicAdd(&g_counter, 1);
        b = __shfl_sync(0xffffffffu, b, 0);
        if (b >= N_BATCH) break;

        const int start = g_seg_start[b];
        const int cnt   = g_seg_start[b + 1] - start;
        const int ngroups = (cnt + 1) >> 1;          // 2 rows per commit group
        const int* eidx = neigh_idx + start;

        // ---- prologue: up to 4 groups of 2 rows
        #pragma unroll
        for (int gj = 0; gj < 4; ++gj) {
            if (gj < ngroups) {
                const int r0 = 2 * gj;
                const int n0 = __ldg(eidx + r0);
                cp16(smem_u32(&buf[w][r0][lane]), fbase + (size_t)n0 * ROW_B + col);
                if (r0 + 1 < cnt) {
                    const int n1 = __ldg(eidx + r0 + 1);
                    cp16(smem_u32(&buf[w][r0 + 1][lane]), fbase + (size_t)n1 * ROW_B + col);
                }
                cp_commit();
            }
        }

        float2 acc0 = make_float2(0.f, 0.f);
        float2 acc1 = make_float2(0.f, 0.f);
        float2 acc2 = make_float2(0.f, 0.f);
        float2 acc3 = make_float2(0.f, 0.f);

        auto accum_pair = [&](float4 A, float4 B) {
            const __half2* ha = reinterpret_cast<const __half2*>(&A);
            const __half2* hb = reinterpret_cast<const __half2*>(&B);
            float2 p;
            p = __half22float2(__hadd2(ha[0], hb[0])); acc0.x += p.x; acc0.y += p.y;
            p = __half22float2(__hadd2(ha[1], hb[1])); acc1.x += p.x; acc1.y += p.y;
            p = __half22float2(__hadd2(ha[2], hb[2])); acc2.x += p.x; acc2.y += p.y;
            p = __half22float2(__hadd2(ha[3], hb[3])); acc3.x += p.x; acc3.y += p.y;
        };
        auto accum_one = [&](float4 A) {
            const __half2* ha = reinterpret_cast<const __half2*>(&A);
            float2 p;
            p = __half22float2(ha[0]); acc0.x += p.x; acc0.y += p.y;
            p = __half22float2(ha[1]); acc1.x += p.x; acc1.y += p.y;
            p = __half22float2(ha[2]); acc2.x += p.x; acc2.y += p.y;
            p = __half22float2(ha[3]); acc3.x += p.x; acc3.y += p.y;
        };

        // ---- steady state: wait_group 3, consume 2 rows pairwise,
        // refill with group g+4, indices prefetched one iteration ahead.
        int g = 0;
        int nx0 = 0, nx1 = 0;
        if (4 < ngroups) {
            nx0 = __ldg(eidx + 8);
            nx1 = (9 < cnt) ? __ldg(eidx + 9) : nx0;
        }
        #pragma unroll 1
        for (; g + 4 < ngroups; ++g) {
            asm volatile("cp.async.wait_group 3;" ::: "memory");
            const int s0 = (2 * g) & (STAGES - 1);
            const float4 f0 = buf[w][s0][lane];
            const float4 f1 = buf[w][s0 + 1][lane];

            const int rr = 2 * (g + 4);
            cp16(smem_u32(&buf[w][s0][lane]), fbase + (size_t)nx0 * ROW_B + col);
            if (rr + 1 < cnt)
                cp16(smem_u32(&buf[w][s0 + 1][lane]), fbase + (size_t)nx1 * ROW_B + col);
            cp_commit();

            if (g + 5 < ngroups) {
                const int rn = 2 * (g + 5);
                nx0 = __ldg(eidx + rn);
                nx1 = (rn + 1 < cnt) ? __ldg(eidx + rn + 1) : nx0;
            }

            accum_pair(f0, f1);
        }

        // ---- tail: drain, consume rows [2g, cnt)
        asm volatile("cp.async.wait_group 0;" ::: "memory");
        int r = 2 * g;
        #pragma unroll 1
        for (; r + 1 < cnt; r += 2)
            accum_pair(buf[w][r & (STAGES - 1)][lane],
                       buf[w][(r + 1) & (STAGES - 1)][lane]);
        if (r < cnt)
            accum_one(buf[w][r & (STAGES - 1)][lane]);

        const float inv = 1.0f / fmaxf((float)cnt, 1.0f);
        const float4 agg0 = make_float4(acc0.x * inv, acc0.y * inv, acc1.x * inv, acc1.y * inv);
        const float4 agg1 = make_float4(acc2.x * inv, acc2.y * inv, acc3.x * inv, acc3.y * inv);

        const float4* sp = reinterpret_cast<const float4*>(self_feats + (size_t)b * D_FEAT) + 2 * lane;
        const float4 s0 = __ldcs(sp);
        const float4 s1 = __ldcs(sp + 1);
        const float4 d0 = make_float4(s0.x - agg0.x, s0.y - agg0.y, s0.z - agg0.z, s0.w - agg0.w);
        const float4 d1 = make_float4(s1.x - agg1.x, s1.y - agg1.y, s1.z - agg1.z, s1.w - agg1.w);

        float* orow = out + (size_t)b * (2 * D_FEAT);
        __stcs(reinterpret_cast<float4*>(orow) + 2 * lane, d0);
        __stcs(reinterpret_cast<float4*>(orow) + 2 * lane + 1, d1);
        __stcs(reinterpret_cast<float4*>(orow + D_FEAT) + 2 * lane, agg0);
        __stcs(reinterpret_cast<float4*>(orow + D_FEAT) + 2 * lane + 1, agg1);
    }
}

extern "C" void kernel_launch(void* const* d_in, const int* in_sizes, int n_in,
                              void* d_out, int out_size)
{
    const float* features   = (const float*)d_in[0];
    const int*   neigh_idx  = (const int*)d_in[1];
    const int*   seg_ids    = (const int*)d_in[2];
    const float* self_feats = (const float*)d_in[3];
    float*       out        = (float*)d_out;

    const int n_edges = in_sizes[1];
    const int n16 = in_sizes[0] / 16;

    const int prep_threads = (n16 > n_edges) ? n16 : n_edges;
    prep_kernel<<<(prep_threads + 255) / 256, 256>>>(features, n16, seg_ids, n_edges);
    intra_agg_kernel<<<CTAS_RES, TPB>>>(neigh_idx, self_feats, out);
}

// round 16
// speedup vs baseline: 1.2009x; 1.2009x over previous
#include <cuda_runtime.h>
#include <cuda_bf16.h>

// IntraAgg: segment-mean neighbor aggregation (f32 single-pass, L2-cap path).
// R7 proven shape + evict-first streaming epilogue (protect features in L2).
//   d_in[0] features    float32 [100000*256]
//   d_in[1] neigh_idx   int32   [524288]
//   d_in[2] segment_ids int32   [524288] (sorted ascending)
//   d_in[3] self_feats  float32 [16384*256]
// output: float32 [16384*512] = concat(self - agg, agg)

#define D_FEAT   256
#define TPB      64               // one float4 (16B) per thread per row
#define N_BATCH  16384
#define STAGES   8                // ring: 8 rows = 4 groups of 2 (8KB smem)

__device__ int g_seg_start[N_BATCH + 1];

__global__ void seg_bounds_kernel(const int* __restrict__ seg_ids, int n_edges)
{
    const int e = blockIdx.x * blockDim.x + threadIdx.x;
    if (e >= n_edges) return;
    const int s_cur  = __ldg(seg_ids + e);
    const int s_prev = (e == 0) ? -1 : __ldg(seg_ids + e - 1);
    for (int b = s_prev + 1; b <= s_cur; ++b)
        g_seg_start[b] = e;
    if (e == n_edges - 1)
        for (int b = s_cur + 1; b <= N_BATCH; ++b)
            g_seg_start[b] = n_edges;
}

__device__ __forceinline__ unsigned int smem_u32(const void* p)
{
    return (unsigned int)__cvta_generic_to_shared(p);
}

__device__ __forceinline__ void cp16(unsigned int dst, const void* src)
{
    asm volatile("cp.async.cg.shared.global [%0], [%1], 16;"
                 :: "r"(dst), "l"(src) : "memory");
}

__device__ __forceinline__ void cp_commit()
{
    asm volatile("cp.async.commit_group;" ::: "memory");
}

__global__ __launch_bounds__(TPB) void intra_agg_kernel(
    const float* __restrict__ features,
    const int* __restrict__ neigh_idx,
    const float* __restrict__ self_feats,
    float* __restrict__ out)
{
    // thread t owns column t of every slot: no cross-thread smem sharing,
    // hence no __syncthreads / mbarrier anywhere. (R7 proven shape.)
    __shared__ __align__(16) float4 buf[STAGES][TPB];

    const int b   = blockIdx.x;
    const int tid = threadIdx.x;

    const int start = g_seg_start[b];
    const int cnt   = g_seg_start[b + 1] - start;
    const int ngroups = (cnt + 1) >> 1;      // groups of 2 rows (last may be 1)

    const char* fbase = reinterpret_cast<const char*>(features);
    const size_t col_off = (size_t)tid * 16;

    // ---- prologue: issue up to 4 groups (8 rows), one commit per group
    #pragma unroll
    for (int gj = 0; gj < 4; ++gj) {
        if (gj < ngroups) {
            const int r0 = 2 * gj;
            const int n0 = __ldg(neigh_idx + start + r0);
            cp16(smem_u32(&buf[r0][tid]), fbase + (size_t)n0 * (D_FEAT * 4) + col_off);
            if (r0 + 1 < cnt) {
                const int n1 = __ldg(neigh_idx + start + r0 + 1);
                cp16(smem_u32(&buf[r0 + 1][tid]), fbase + (size_t)n1 * (D_FEAT * 4) + col_off);
            }
            cp_commit();
        }
    }

    float4 acc0 = make_float4(0.f, 0.f, 0.f, 0.f);
    float4 acc1 = make_float4(0.f, 0.f, 0.f, 0.f);

    // ---- steady state over full groups; group g ready after wait_group 3.
    int g = 0;
    int nx0 = 0, nx1 = 0;
    if (4 < ngroups) {
        nx0 = __ldg(neigh_idx + start + 8);
        nx1 = (9 < cnt) ? __ldg(neigh_idx + start + 9) : nx0;
    }
    #pragma unroll 1
    for (; g + 4 < ngroups; ++g) {
        asm volatile("cp.async.wait_group 3;" ::: "memory");
        const int r = 2 * g;
        const int s0 = r & (STAGES - 1);
        const float4 f0 = buf[s0][tid];
        const float4 f1 = buf[s0 + 1][tid];

        const int rr = 2 * (g + 4);
        cp16(smem_u32(&buf[s0][tid]), fbase + (size_t)nx0 * (D_FEAT * 4) + col_off);
        if (rr + 1 < cnt)
            cp16(smem_u32(&buf[s0 + 1][tid]), fbase + (size_t)nx1 * (D_FEAT * 4) + col_off);
        cp_commit();

        if (g + 5 < ngroups) {
            const int rn = 2 * (g + 5);
            nx0 = __ldg(neigh_idx + start + rn);
            nx1 = (rn + 1 < cnt) ? __ldg(neigh_idx + start + rn + 1) : nx0;
        }

        acc0.x += f0.x; acc0.y += f0.y; acc0.z += f0.z; acc0.w += f0.w;
        acc1.x += f1.x; acc1.y += f1.y; acc1.z += f1.z; acc1.w += f1.w;
    }

    // ---- tail: drain everything, consume rows [2g, cnt)
    asm volatile("cp.async.wait_group 0;" ::: "memory");
    #pragma unroll 1
    for (int r = 2 * g; r < cnt; ++r) {
        const float4 f = buf[r & (STAGES - 1)][tid];
        if (r & 1) { acc1.x += f.x; acc1.y += f.y; acc1.z += f.z; acc1.w += f.w; }
        else       { acc0.x += f.x; acc0.y += f.y; acc0.z += f.z; acc0.w += f.w; }
    }

    float4 agg;
    const float inv = 1.0f / fmaxf((float)cnt, 1.0f);
    agg.x = (acc0.x + acc1.x) * inv;
    agg.y = (acc0.y + acc1.y) * inv;
    agg.z = (acc0.z + acc1.z) * inv;
    agg.w = (acc0.w + acc1.w) * inv;

    // evict-first epilogue: the 48MB self/out stream must not displace the
    // ~102MB features working set from L2 (re-miss fill traffic eats the
    // binding LTS bandwidth).
    const float4 s = __ldcs(reinterpret_cast<const float4*>(self_feats + (size_t)b * D_FEAT) + tid);
    float4 diff;
    diff.x = s.x - agg.x; diff.y = s.y - agg.y;
    diff.z = s.z - agg.z; diff.w = s.w - agg.w;

    float* orow = out + (size_t)b * (2 * D_FEAT);
    __stcs(reinterpret_cast<float4*>(orow) + tid, diff);
    __stcs(reinterpret_cast<float4*>(orow + D_FEAT) + tid, agg);
}

extern "C" void kernel_launch(void* const* d_in, const int* in_sizes, int n_in,
                              void* d_out, int out_size)
{
    const float* features   = (const float*)d_in[0];
    const int*   neigh_idx  = (const int*)d_in[1];
    const int*   seg_ids    = (const int*)d_in[2];
    const float* self_feats = (const float*)d_in[3];
    float*       out        = (float*)d_out;

    const int n_edges = in_sizes[1];
    const int n_batch = in_sizes[3] / D_FEAT;   // 16384

    seg_bounds_kernel<<<(n_edges + 255) / 256, 256>>>(seg_ids, n_edges);
    intra_agg_kernel<<<n_batch, TPB>>>(features, neigh_idx, self_feats, out);
}